// round 14
// baseline (speedup 1.0000x reference)
#include <cuda_runtime.h>
#include <cstdint>

// ---------------------------------------------------------------------------
// RSSMCore: T=64 sequential steps, B=256.  PASSING MODEL (locked since R6):
//  * RNG: jax_threefry_partitionable: bits(i) = o0^o1 of threefry(key,(0,i)).
//  * GEMM: exact f32, per-output ascending-k single-accumulator FMA chain
//    (BK=16 tiles ascending) — flip-free at rel_err 9.051719e-07.
//    Per-output arithmetic MUST NOT change.
//  * z weights w = fl(1+p)-p carried into the W_in gather.
//  * XLA rational tanh / logistic / cephes exp/log, FMA-form.
// R13 kept: per-step pipeline (counter sync, dependency-ordered roles),
//           32x64 chain tiles / 64x128 bulk tiles, double buffering.
// Round 14 (perf only):
//  * GEMM inner loop via PTX fma.rn.f32x2 (FFMA2): one packed instruction =
//    2 independent IEEE fp32 fma.rn ops -> bit-identical per-output chains,
//    but escapes the FFMA-3reg register-bank ceiling (rt 2 -> packed pair).
//    A staged DUPLICATED as (a,a) 64-bit pairs in smem (broadcast multiplier
//    = one LDS, no packing MOVs); W pairs fall out of the row layout.
//  * gru fused into step_kernel as role 0 (grid 192x8) - one less launch.
// ---------------------------------------------------------------------------

#define T_STEPS 64
#define B 256
#define GRU_H 2048
#define MLP 1000
#define ZF 1024
#define FDIM 1024
#define G3 (3 * GRU_H)   // 6144

// ---------------- scratch (device globals; no allocation allowed) ----------
__device__ float g_x[B * MLP];
__device__ float g_gi[B * G3];
__device__ float g_gh[B * G3];
__device__ float g_h[B * GRU_H];
__device__ float g_p1[B * MLP];
__device__ float g_q1[B * MLP];
__device__ int   g_cnt[T_STEPS][5];   // 0:gru 1:q1 2:p1 3:post 4:x

// =================== XLA-matched elementwise math (FMA form) ================

__device__ __forceinline__ float xla_tanh(float x) {
    if (fabsf(x) < 0.0004f) return x;
    float xc = fminf(fmaxf(x, -7.90531110763549805f), 7.90531110763549805f);
    float x2 = __fmul_rn(xc, xc);
    float p = -2.76076847742355e-16f;
    p = __fmaf_rn(p, x2, 2.00018790482477e-13f);
    p = __fmaf_rn(p, x2, -8.60467152213735e-11f);
    p = __fmaf_rn(p, x2, 5.12229709037114e-08f);
    p = __fmaf_rn(p, x2, 1.48572235717979e-05f);
    p = __fmaf_rn(p, x2, 6.37261928875436e-04f);
    p = __fmaf_rn(p, x2, 4.89352455891786e-03f);
    p = __fmul_rn(p, xc);
    float q = 1.19825839466702e-06f;
    q = __fmaf_rn(q, x2, 1.18534705686654e-04f);
    q = __fmaf_rn(q, x2, 2.26843463243900e-03f);
    q = __fmaf_rn(q, x2, 4.89352518554385e-03f);
    return __fdiv_rn(p, q);
}

__device__ __forceinline__ float xla_sigmoid(float x) {
    return __fmaf_rn(0.5f, xla_tanh(__fmul_rn(0.5f, x)), 0.5f);
}

__device__ __forceinline__ float xla_log(float a) {
    int ix = __float_as_int(a);
    float e = (float)((ix >> 23) - 126);
    float m = __int_as_float((ix & 0x007fffff) | 0x3f000000);
    if (m < 0.707106781186547524f) { e = __fadd_rn(e, -1.0f); m = __fadd_rn(m, m); }
    m = __fadd_rn(m, -1.0f);
    float z = __fmul_rn(m, m);
    float y = 7.0376836292e-2f;
    y = __fmaf_rn(y, m, -1.1514610310e-1f);
    y = __fmaf_rn(y, m, 1.1676998740e-1f);
    y = __fmaf_rn(y, m, -1.2420140846e-1f);
    y = __fmaf_rn(y, m, 1.4249322787e-1f);
    y = __fmaf_rn(y, m, -1.6668057665e-1f);
    y = __fmaf_rn(y, m, 2.0000714765e-1f);
    y = __fmaf_rn(y, m, -2.4999993993e-1f);
    y = __fmaf_rn(y, m, 3.3333331174e-1f);
    y = __fmul_rn(__fmul_rn(y, m), z);
    y = __fmaf_rn(e, -2.12194440e-4f, y);
    y = __fmaf_rn(z, -0.5f, y);
    float r = __fadd_rn(m, y);
    r = __fmaf_rn(e, 0.693359375f, r);
    return r;
}

__device__ __forceinline__ float xla_exp(float x) {
    float xc = fminf(fmaxf(x, -87.33654f), 88.72283f);
    float m = floorf(__fmaf_rn(xc, 1.44269504088896341f, 0.5f));
    float r = __fmaf_rn(m, -0.693359375f, xc);
    r = __fmaf_rn(m, 2.12194440e-4f, r);
    float r2 = __fmul_rn(r, r);
    float p = 1.9875691500e-4f;
    p = __fmaf_rn(p, r, 1.3981999507e-3f);
    p = __fmaf_rn(p, r, 8.3334519073e-3f);
    p = __fmaf_rn(p, r, 4.1665795894e-2f);
    p = __fmaf_rn(p, r, 1.6666665459e-1f);
    p = __fmaf_rn(p, r, 5.0000001201e-1f);
    float y = __fadd_rn(__fmaf_rn(p, r2, r), 1.0f);
    return __fmul_rn(y, __int_as_float(((int)m + 127) << 23));
}

__device__ __forceinline__ float xla_expm1(float x) {
    if (fabsf(x) < 1e-5f) return __fmaf_rn(__fmul_rn(0.5f, x), x, x);
    return __fadd_rn(xla_exp(x), -1.0f);
}

__device__ __forceinline__ float xla_elu(float x) {
    return (x > 0.0f) ? x : xla_expm1(x);
}

// ---------------- threefry2x32 (JAX bit-exact) ------------------------------
__device__ __forceinline__ uint32_t rotl32(uint32_t v, int r) {
    return (v << r) | (v >> (32 - r));
}

__device__ __forceinline__ void threefry2x32(uint32_t k0, uint32_t k1,
                                             uint32_t x0, uint32_t x1,
                                             uint32_t& o0, uint32_t& o1) {
    uint32_t ks2 = k0 ^ k1 ^ 0x1BD11BDAu;
    x0 += k0; x1 += k1;
    x0 += x1; x1 = rotl32(x1, 13); x1 ^= x0;
    x0 += x1; x1 = rotl32(x1, 15); x1 ^= x0;
    x0 += x1; x1 = rotl32(x1, 26); x1 ^= x0;
    x0 += x1; x1 = rotl32(x1,  6); x1 ^= x0;
    x0 += k1; x1 += ks2 + 1u;
    x0 += x1; x1 = rotl32(x1, 17); x1 ^= x0;
    x0 += x1; x1 = rotl32(x1, 29); x1 ^= x0;
    x0 += x1; x1 = rotl32(x1, 16); x1 ^= x0;
    x0 += x1; x1 = rotl32(x1, 24); x1 ^= x0;
    x0 += ks2; x1 += k0 + 2u;
    x0 += x1; x1 = rotl32(x1, 13); x1 ^= x0;
    x0 += x1; x1 = rotl32(x1, 15); x1 ^= x0;
    x0 += x1; x1 = rotl32(x1, 26); x1 ^= x0;
    x0 += x1; x1 = rotl32(x1,  6); x1 ^= x0;
    x0 += k0; x1 += k1 + 3u;
    x0 += x1; x1 = rotl32(x1, 17); x1 ^= x0;
    x0 += x1; x1 = rotl32(x1, 29); x1 ^= x0;
    x0 += x1; x1 = rotl32(x1, 16); x1 ^= x0;
    x0 += x1; x1 = rotl32(x1, 24); x1 ^= x0;
    x0 += k1; x1 += ks2 + 4u;
    x0 += x1; x1 = rotl32(x1, 13); x1 ^= x0;
    x0 += x1; x1 = rotl32(x1, 15); x1 ^= x0;
    x0 += x1; x1 = rotl32(x1, 26); x1 ^= x0;
    x0 += x1; x1 = rotl32(x1,  6); x1 ^= x0;
    x0 += ks2; x1 += k0 + 5u;
    o0 = x0; o1 = x1;
}

__device__ __forceinline__ uint32_t jax_bits32(uint32_t k0, uint32_t k1, uint32_t i) {
    uint32_t o0, o1;
    threefry2x32(k0, k1, 0u, i, o0, o1);
    return o0 ^ o1;
}

// ---------------- packed f32x2 helpers ---------------------------------------
// One FFMA2 = two independent IEEE fp32 fma.rn (low/high 32-bit halves) —
// bit-identical per-element to __fmaf_rn; escapes the 3-reg FFMA bank limit.
__device__ __forceinline__ unsigned long long ffma2(
    unsigned long long a, unsigned long long w, unsigned long long c) {
    unsigned long long d;
    asm("fma.rn.f32x2 %0, %1, %2, %3;" : "=l"(d) : "l"(a), "l"(w), "l"(c));
    return d;
}

__device__ __forceinline__ unsigned long long pack2dup(float v) {
    unsigned long long p;
    uint32_t u = __float_as_uint(v);
    asm("mov.b64 %0, {%1, %1};" : "=l"(p) : "r"(u));
    return p;
}

__device__ __forceinline__ float2 unpack2(unsigned long long p) {
    float2 r;
    r.x = __uint_as_float((uint32_t)p);
    r.y = __uint_as_float((uint32_t)(p >> 32));
    return r;
}

// ---------------- counter sync helpers --------------------------------------
__device__ __forceinline__ void role_signal(int t, int slot) {
    __threadfence();
    __syncthreads();
    if (threadIdx.x == 0) atomicAdd(&g_cnt[t][slot], 1);
}

__device__ __forceinline__ void role_wait(int t, int slot, int target) {
    if (threadIdx.x == 0) {
        while (atomicAdd(&g_cnt[t][slot], 0) < target) __nanosleep(64);
        __threadfence();
    }
    __syncthreads();
}

// ---------------- guarded float4 load ---------------------------------------
__device__ __forceinline__ float4 load_f4_guard(const float* __restrict__ src,
                                                size_t base, int k, int Klim) {
    if (k + 3 < Klim) return *reinterpret_cast<const float4*>(&src[base]);
    float4 v;
    v.x = (k + 0 < Klim) ? src[base + 0] : 0.f;
    v.y = (k + 1 < Klim) ? src[base + 1] : 0.f;
    v.z = (k + 2 < Klim) ? src[base + 2] : 0.f;
    v.w = (k + 3 < Klim) ? src[base + 3] : 0.f;
    return v;
}

// ---------------- templated GEMM core: BMxBN, FFMA2, double-buffered ---------
// Per-output arithmetic: locked ascending-k single-accumulator fma.rn chain
// over BK=16 tiles — per-element identical to R11/R12/R13 (FFMA2 halves are
// independent fp32 fma.rn ops; pairing is over adjacent N-columns).
#define SMEM_BYTES 33792   // sizeof largest variant (64x128)

template<int BM, int BN>
__device__ void gemm_core_t(char* smraw,
    const float* __restrict__ A, const float* __restrict__ W,
    const float* __restrict__ bias, float* __restrict__ C,
    int K, int N, bool act, bool fuse,
    const float* __restrict__ feat, int concatK, int bm, int bn)
{
    // As2 holds (a,a) duplicated 64-bit pairs -> broadcast multiplier = 1 LDS.
    struct Sm { unsigned long long As2[2][16][BM + 4]; float Ws[2][16][BN]; };
    Sm* sm = reinterpret_cast<Sm*>(smraw);
    constexpr int TM = BM / 16;          // rows/thread: 4 or 2
    constexpr int TN = BN / 16;          // cols/thread: 8 or 4
    constexpr int NP = TN / 2;           // acc pairs: 4 or 2
    constexpr int NW = BN / 64;          // W float4 loads per thread: 2 or 1
    const int lda = fuse ? concatK : K;
    const int tid = threadIdx.x;
    const int tx = tid & 15;
    const int ty = tid >> 4;
    const int arow = tid >> 2, ac4 = tid & 3;          // A staging (tid < BM*4)
    const int wrow  = (NW == 2) ? (tid >> 5) : (tid >> 4);
    const int wcol4 = (NW == 2) ? (tid & 31) : (tid & 15);

    unsigned long long acc[TM][NP];      // (col even, col odd) fp32 pairs
#pragma unroll
    for (int i = 0; i < TM; i++)
#pragma unroll
        for (int j = 0; j < NP; j++) acc[i][j] = 0ull;   // two +0.0f

    const int ntiles = (K + 15) >> 4;

    float4 aR, wR0, wR1;
    auto load_tile = [&](int k0) {
        if (BM * 4 == 256 || tid < BM * 4) {
            int ka = k0 + ac4 * 4;
            if (fuse && ka >= concatK)
                aR = load_f4_guard(feat, (size_t)(bm + arow) * FDIM + (ka - concatK), ka, K);
            else
                aR = load_f4_guard(A, (size_t)(bm + arow) * lda + ka, ka, K);
        }
        int col = bn + wcol4 * 4;
        int kw0 = k0 + wrow;
        if (kw0 < K) {
            if (col + 3 < N) wR0 = *reinterpret_cast<const float4*>(&W[(size_t)kw0 * N + col]);
            else wR0 = load_f4_guard(W, (size_t)kw0 * N + col, col, N);
        } else wR0 = make_float4(0.f, 0.f, 0.f, 0.f);
        if (NW == 2) {
            int kw1 = k0 + wrow + 8;
            if (kw1 < K) {
                if (col + 3 < N) wR1 = *reinterpret_cast<const float4*>(&W[(size_t)kw1 * N + col]);
                else wR1 = load_f4_guard(W, (size_t)kw1 * N + col, col, N);
            } else wR1 = make_float4(0.f, 0.f, 0.f, 0.f);
        }
    };
    auto store_tile = [&](int buf) {
        if (BM * 4 == 256 || tid < BM * 4) {
            sm->As2[buf][ac4 * 4 + 0][arow] = pack2dup(aR.x);
            sm->As2[buf][ac4 * 4 + 1][arow] = pack2dup(aR.y);
            sm->As2[buf][ac4 * 4 + 2][arow] = pack2dup(aR.z);
            sm->As2[buf][ac4 * 4 + 3][arow] = pack2dup(aR.w);
        }
        *reinterpret_cast<float4*>(&sm->Ws[buf][wrow][wcol4 * 4]) = wR0;
        if (NW == 2)
            *reinterpret_cast<float4*>(&sm->Ws[buf][wrow + 8][wcol4 * 4]) = wR1;
    };

    load_tile(0);
    store_tile(0);
    __syncthreads();

    int buf = 0;
    for (int tI = 0; tI < ntiles; tI++) {
        const bool more = (tI + 1 < ntiles);
        if (more) load_tile((tI + 1) << 4);

#pragma unroll
        for (int kk = 0; kk < 16; kk++) {
            unsigned long long ap[TM];
            if (TM == 4) {
                ulonglong2 a01 = *reinterpret_cast<const ulonglong2*>(&sm->As2[buf][kk][ty * 4]);
                ulonglong2 a23 = *reinterpret_cast<const ulonglong2*>(&sm->As2[buf][kk][ty * 4 + 2]);
                ap[0] = a01.x; ap[1] = a01.y; ap[2] = a23.x; ap[TM - 1] = a23.y;
            } else {
                ulonglong2 a01 = *reinterpret_cast<const ulonglong2*>(&sm->As2[buf][kk][ty * 2]);
                ap[0] = a01.x; ap[TM - 1] = a01.y;
            }
            unsigned long long wp[NP];
            {
                ulonglong2 w01 = *reinterpret_cast<const ulonglong2*>(&sm->Ws[buf][kk][tx * 4]);
                wp[0] = w01.x; wp[1] = w01.y;
            }
            if (NP == 4) {
                ulonglong2 w23 = *reinterpret_cast<const ulonglong2*>(&sm->Ws[buf][kk][64 + tx * 4]);
                wp[NP - 2] = w23.x; wp[NP - 1] = w23.y;
            }
#pragma unroll
            for (int i = 0; i < TM; i++)
#pragma unroll
                for (int j = 0; j < NP; j++)
                    acc[i][j] = ffma2(ap[i], wp[j], acc[i][j]);
        }
        if (more) {
            store_tile(buf ^ 1);
            __syncthreads();
            buf ^= 1;
        }
    }

    const bool fullN = (bn + BN <= N);
#pragma unroll
    for (int i = 0; i < TM; i++) {
        int row = bm + ty * TM + i;
#pragma unroll
        for (int h = 0; h < NW; h++) {
            int colb = bn + h * 64 + tx * 4;
            float2 u0 = unpack2(acc[i][h * 2 + 0]);
            float2 u1 = unpack2(acc[i][h * 2 + 1]);
            float v[4] = {u0.x, u0.y, u1.x, u1.y};
#pragma unroll
            for (int j = 0; j < 4; j++) {
                int col = colb + j;
                if (col < N) {
                    if (bias) v[j] = __fadd_rn(v[j], bias[col]);
                    if (act) v[j] = xla_elu(v[j]);
                }
            }
            if (fullN) {
                *reinterpret_cast<float4*>(&C[(size_t)row * N + colb]) =
                    make_float4(v[0], v[1], v[2], v[3]);
            } else {
#pragma unroll
                for (int j = 0; j < 4; j++)
                    if (colb + j < N) C[(size_t)row * N + colb + j] = v[j];
            }
        }
    }
}

// ---------------- gru element (identical arithmetic to R11..R13) -------------
__device__ __forceinline__ void gru_elem(int i4) {
    int b = i4 >> 9;
    int j4 = i4 & 511;
    const float4* gib = reinterpret_cast<const float4*>(g_gi + (size_t)b * G3);
    const float4* ghb = reinterpret_cast<const float4*>(g_gh + (size_t)b * G3);
    float4 ir4 = gib[j4],        hr4 = ghb[j4];
    float4 iz4 = gib[512 + j4],  hz4 = ghb[512 + j4];
    float4 in4 = gib[1024 + j4], hn4 = ghb[1024 + j4];
    float4 hp4 = reinterpret_cast<const float4*>(g_h)[i4];
    float4 o;
    {
        float r  = xla_sigmoid(__fadd_rn(ir4.x, hr4.x));
        float zg = xla_sigmoid(__fadd_rn(iz4.x, hz4.x));
        float n  = xla_tanh(__fmaf_rn(r, hn4.x, in4.x));
        o.x = __fmaf_rn(zg, hp4.x, __fmul_rn(__fsub_rn(1.0f, zg), n));
    }
    {
        float r  = xla_sigmoid(__fadd_rn(ir4.y, hr4.y));
        float zg = xla_sigmoid(__fadd_rn(iz4.y, hz4.y));
        float n  = xla_tanh(__fmaf_rn(r, hn4.y, in4.y));
        o.y = __fmaf_rn(zg, hp4.y, __fmul_rn(__fsub_rn(1.0f, zg), n));
    }
    {
        float r  = xla_sigmoid(__fadd_rn(ir4.z, hr4.z));
        float zg = xla_sigmoid(__fadd_rn(iz4.z, hz4.z));
        float n  = xla_tanh(__fmaf_rn(r, hn4.z, in4.z));
        o.z = __fmaf_rn(zg, hp4.z, __fmul_rn(__fsub_rn(1.0f, zg), n));
    }
    {
        float r  = xla_sigmoid(__fadd_rn(ir4.w, hr4.w));
        float zg = xla_sigmoid(__fadd_rn(iz4.w, hz4.w));
        float n  = xla_tanh(__fmaf_rn(r, hn4.w, in4.w));
        o.w = __fmaf_rn(zg, hp4.w, __fmul_rn(__fsub_rn(1.0f, zg), n));
    }
    reinterpret_cast<float4*>(g_h)[i4] = o;
}

// ---------------- per-step pipelined mega-kernel -----------------------------
// grid (192, 8); blockIdx.y = role in dependency order:
//  y0 gru(192) | y1 q1(32x64,128, wait gru) | y2 gh(64x128,192, wait gru) |
//  y3 p1(64x128,32, wait gru) | y4 post(32x64,128, wait q1) |
//  y5 prior(64x128,32, wait p1) | y6 sample+x(128, wait post) |
//  y7 gi(64x128,192, wait x)
__global__ __launch_bounds__(256) void step_kernel(
    const float* __restrict__ W_ih, const float* __restrict__ W_hh,
    const float* __restrict__ Wp1,  const float* __restrict__ Wq1,
    const float* __restrict__ Wp2,  const float* __restrict__ Wq2,
    const float* __restrict__ b_ih, const float* __restrict__ b_hh,
    const float* __restrict__ bp1,  const float* __restrict__ bq1,
    const float* __restrict__ bp2,  const float* __restrict__ bq2,
    const float* __restrict__ W_in, const float* __restrict__ b_in,
    const int* __restrict__ actions,
    const float* __restrict__ feat,
    float* __restrict__ out_prior, float* __restrict__ out_post,
    int t, int last)
{
    __shared__ __align__(16) char smraw[SMEM_BYTES];
    const int role = blockIdx.y;
    const int bid = blockIdx.x;            // 0..191

    if (role == 0) {        // gru: h_t = gru(gi_t, gh_t, h_{t-1})
        const int total = B * GRU_H / 4;   // 131072 float4 units
        for (int i4 = bid * 256 + threadIdx.x; i4 < total; i4 += 192 * 256)
            gru_elem(i4);
        role_signal(t, 0);
    } else if (role == 1) { // q1 = elu([h|feat] @ Wq1 + bq1)  K=3072, N=1000
        if (bid >= 128) return;
        role_wait(t, 0, 192);
        int bm = (bid & 7) * 32, bn = (bid >> 3) * 64;
        gemm_core_t<32, 64>(smraw, g_h, Wq1, bq1, g_q1, GRU_H + FDIM, MLP,
                            true, true, feat, GRU_H, bm, bn);
        role_signal(t, 1);
    } else if (role == 2) { // gh_{t+1} = h @ W_hh + b_hh      K=2048, N=6144
        if (last) return;
        role_wait(t, 0, 192);
        gemm_core_t<64, 128>(smraw, g_h, W_hh, b_hh, g_gh, GRU_H, G3,
                             false, false, nullptr, 0, (bid & 3) * 64, (bid >> 2) * 128);
    } else if (role == 3) { // p1 = elu(h @ Wp1 + bp1)         K=2048, N=1000
        if (bid >= 32) return;
        role_wait(t, 0, 192);
        gemm_core_t<64, 128>(smraw, g_h, Wp1, bp1, g_p1, GRU_H, MLP,
                             true, false, nullptr, 0, (bid & 3) * 64, (bid >> 2) * 128);
        role_signal(t, 2);
    } else if (role == 4) { // post = q1 @ Wq2 + bq2           K=1000, N=1024
        if (bid >= 128) return;
        role_wait(t, 1, 128);
        int bm = (bid & 7) * 32, bn = (bid >> 3) * 64;
        gemm_core_t<32, 64>(smraw, g_q1, Wq2, bq2, out_post, MLP, ZF,
                            false, false, nullptr, 0, bm, bn);
        role_signal(t, 3);
    } else if (role == 5) { // prior = p1 @ Wp2 + bp2          K=1000, N=1024
        if (bid >= 32) return;
        role_wait(t, 2, 32);
        gemm_core_t<64, 128>(smraw, g_p1, Wp2, bp2, out_prior, MLP, ZF,
                             false, false, nullptr, 0, (bid & 3) * 64, (bid >> 2) * 128);
    } else if (role == 6) { // sample z_t + x_{t+1}  (2 batches per block)
        if (last) return;
        if (bid >= 128) return;
        role_wait(t, 3, 128);

        __shared__ int   idx[2][32];
        __shared__ float wgt[2][32];

        int warp = threadIdx.x >> 5;
        int lane = threadIdx.x & 31;
        int half = warp >> 2;
        int b = bid * 2 + half;
        int cw = warp & 3;

        uint32_t k0, k1;
        threefry2x32(0u, 42u, 0u, (uint32_t)t, k0, k1);
        const float TINY = 1.1754943508222875e-38f;

        for (int c = cw; c < 32; c += 4) {
            float l = out_post[(size_t)b * ZF + c * 32 + lane];
            uint32_t i = (uint32_t)((b * 32 + c) * 32 + lane);
            uint32_t bits = jax_bits32(k0, k1, i);
            float f = __fadd_rn(__uint_as_float((bits >> 9) | 0x3f800000u), -1.0f);
            float u = fmaxf(TINY, __fadd_rn(f, TINY));
            float g = -xla_log(-xla_log(u));
            float v = __fadd_rn(l, g);

            float bv = v; int bi = lane;
#pragma unroll
            for (int off = 16; off > 0; off >>= 1) {
                float ov = __shfl_down_sync(0xffffffffu, bv, off);
                int   oi = __shfl_down_sync(0xffffffffu, bi, off);
                if (ov > bv || (ov == bv && oi < bi)) { bv = ov; bi = oi; }
            }
            bi = __shfl_sync(0xffffffffu, bi, 0);

            float m = l;
#pragma unroll
            for (int off = 16; off > 0; off >>= 1)
                m = fmaxf(m, __shfl_xor_sync(0xffffffffu, m, off));
            float e = xla_exp(__fadd_rn(l, -m));
            float s = 0.f;
#pragma unroll
            for (int ll = 0; ll < 32; ll++)
                s = __fadd_rn(s, __shfl_sync(0xffffffffu, e, ll));
            float p = __fdiv_rn(e, s);
            float psel = __shfl_sync(0xffffffffu, p, bi);
            if (lane == 0) {
                idx[half][c] = bi;
                wgt[half][c] = __fadd_rn(__fadd_rn(1.0f, psel), -psel);  // fl(1+p)-p
            }
        }
        __syncthreads();

        int xh = threadIdx.x >> 7;
        int bx = bid * 2 + xh;
        int a = actions[t * B + bx];        // act_seq[t+1] = actions[t]
        for (int j = threadIdx.x & 127; j < MLP; j += 128) {
            float s = 0.f;
#pragma unroll
            for (int c = 0; c < 32; c++)
                s = __fmaf_rn(wgt[xh][c], W_in[(size_t)(c * 32 + idx[xh][c]) * MLP + j], s);
            s = __fmaf_rn(1.0f, W_in[(size_t)(ZF + a) * MLP + j], s);
            s = __fadd_rn(s, b_in[j]);
            g_x[bx * MLP + j] = xla_elu(s);
        }
        role_signal(t, 4);
    } else {                // role 7: gi_{t+1} = x @ W_ih + b_ih  K=1000, N=6144
        if (last) return;
        role_wait(t, 4, 128);
        gemm_core_t<64, 128>(smraw, g_x, W_ih, b_ih, g_gi, MLP, G3,
                             false, false, nullptr, 0, (bid & 3) * 64, (bid >> 2) * 128);
    }
}

// ---------------- prologue kernels -------------------------------------------
__global__ __launch_bounds__(256) void reset_kernel()
{
    int i = blockIdx.x * blockDim.x + threadIdx.x;
    if (i < T_STEPS * 5) (&g_cnt[0][0])[i] = 0;
    for (int j = i; j < B * GRU_H; j += gridDim.x * blockDim.x) g_h[j] = 0.f;
}

__global__ __launch_bounds__(256) void compute_x0_kernel(
    const float* __restrict__ W_in, const float* __restrict__ b_in)
{
    int b = blockIdx.x;
    for (int j = threadIdx.x; j < MLP; j += blockDim.x) {
        float s = W_in[(size_t)ZF * MLP + j];   // action 0 row, weight 1
        s = __fadd_rn(s, b_in[j]);
        g_x[b * MLP + j] = xla_elu(s);
    }
}

// prologue dual GEMM: gi_0 | gh_0 (z selects), grid (4, 48, 2)
__global__ __launch_bounds__(256) void gemm0_kernel(
    const float* __restrict__ W_ih, const float* __restrict__ W_hh,
    const float* __restrict__ b_ih, const float* __restrict__ b_hh)
{
    __shared__ __align__(16) char smraw[SMEM_BYTES];
    const int bm = blockIdx.x * 64;
    const int bn = blockIdx.y * 128;
    if (blockIdx.z == 0)
        gemm_core_t<64, 128>(smraw, g_x, W_ih, b_ih, g_gi, MLP, G3,
                             false, false, nullptr, 0, bm, bn);
    else
        gemm_core_t<64, 128>(smraw, g_h, W_hh, b_hh, g_gh, GRU_H, G3,
                             false, false, nullptr, 0, bm, bn);
}

// ---------------------------------------------------------------------------
extern "C" void kernel_launch(void* const* d_in, const int* in_sizes, int n_in,
                              void* d_out, int out_size)
{
    const float* features = (const float*)d_in[0];   // [64,256,1024]
    const int*   actions  = (const int*)  d_in[1];   // [64,256]
    const float* W_in = (const float*)d_in[2];
    const float* b_in = (const float*)d_in[3];
    const float* W_ih = (const float*)d_in[4];
    const float* W_hh = (const float*)d_in[5];
    const float* b_ih = (const float*)d_in[6];
    const float* b_hh = (const float*)d_in[7];
    const float* Wp1  = (const float*)d_in[8];
    const float* bp1  = (const float*)d_in[9];
    const float* Wp2  = (const float*)d_in[10];
    const float* bp2  = (const float*)d_in[11];
    const float* Wq1  = (const float*)d_in[12];
    const float* bq1  = (const float*)d_in[13];
    const float* Wq2  = (const float*)d_in[14];
    const float* bq2  = (const float*)d_in[15];
    float* out = (float*)d_out;                      // [2,64,256,32,32]

    reset_kernel<<<(B * GRU_H + 255) / 256, 256>>>();
    compute_x0_kernel<<<B, 256>>>(W_in, b_in);
    gemm0_kernel<<<dim3(4, 48, 2), 256>>>(W_ih, W_hh, b_ih, b_hh);

    for (int t = 0; t < T_STEPS; t++) {
        const float* feat_t = features + (size_t)t * B * FDIM;
        float* out_prior = out + (size_t)t * B * ZF;
        float* out_post  = out + ((size_t)(T_STEPS + t)) * B * ZF;

        step_kernel<<<dim3(192, 8), 256>>>(
            W_ih, W_hh, Wp1, Wq1, Wp2, Wq2,
            b_ih, b_hh, bp1, bq1, bp2, bq2,
            W_in, b_in, actions, feat_t, out_prior, out_post,
            t, (t == T_STEPS - 1) ? 1 : 0);
    }
}

// round 15
// speedup vs baseline: 1.3119x; 1.3119x over previous
#include <cuda_runtime.h>
#include <cstdint>

// ---------------------------------------------------------------------------
// RSSMCore: T=64 sequential steps, B=256.  PASSING MODEL (locked since R6):
//  * RNG: jax_threefry_partitionable: bits(i) = o0^o1 of threefry(key,(0,i)).
//  * GEMM: exact f32, per-output ascending-k single-accumulator FMA chain
//    (BK=16 tiles ascending) — flip-free at rel_err 9.051719e-07.
//    Per-output arithmetic MUST NOT change.
//  * z weights w = fl(1+p)-p carried into the W_in gather.
//  * XLA rational tanh / logistic / cephes exp/log, FMA-form.
// R13 core restored EXACTLY (R14's FFMA2 regressed: smem bloat -> L1-bound).
// Round 15 (perf only):
//  * gru fused into step_kernel as role 0 (kills 64 launches + drains).
//  * exact-sized 1D grid (960 blocks), roles range-decoded in dependency
//    order: gru 128 | q1 128 | gh 192 | p1 32 | post 128 | prior 32 |
//    sample 128 | gi 192. No dead blocks; monotone dispatch preserved.
// ---------------------------------------------------------------------------

#define T_STEPS 64
#define B 256
#define GRU_H 2048
#define MLP 1000
#define ZF 1024
#define FDIM 1024
#define G3 (3 * GRU_H)   // 6144

// ---------------- scratch (device globals; no allocation allowed) ----------
__device__ float g_x[B * MLP];
__device__ float g_gi[B * G3];
__device__ float g_gh[B * G3];
__device__ float g_h[B * GRU_H];
__device__ float g_p1[B * MLP];
__device__ float g_q1[B * MLP];
__device__ int   g_cnt[T_STEPS][5];   // 0:gru 1:q1 2:p1 3:post 4:x

// =================== XLA-matched elementwise math (FMA form) ================

__device__ __forceinline__ float xla_tanh(float x) {
    if (fabsf(x) < 0.0004f) return x;
    float xc = fminf(fmaxf(x, -7.90531110763549805f), 7.90531110763549805f);
    float x2 = __fmul_rn(xc, xc);
    float p = -2.76076847742355e-16f;
    p = __fmaf_rn(p, x2, 2.00018790482477e-13f);
    p = __fmaf_rn(p, x2, -8.60467152213735e-11f);
    p = __fmaf_rn(p, x2, 5.12229709037114e-08f);
    p = __fmaf_rn(p, x2, 1.48572235717979e-05f);
    p = __fmaf_rn(p, x2, 6.37261928875436e-04f);
    p = __fmaf_rn(p, x2, 4.89352455891786e-03f);
    p = __fmul_rn(p, xc);
    float q = 1.19825839466702e-06f;
    q = __fmaf_rn(q, x2, 1.18534705686654e-04f);
    q = __fmaf_rn(q, x2, 2.26843463243900e-03f);
    q = __fmaf_rn(q, x2, 4.89352518554385e-03f);
    return __fdiv_rn(p, q);
}

__device__ __forceinline__ float xla_sigmoid(float x) {
    return __fmaf_rn(0.5f, xla_tanh(__fmul_rn(0.5f, x)), 0.5f);
}

__device__ __forceinline__ float xla_log(float a) {
    int ix = __float_as_int(a);
    float e = (float)((ix >> 23) - 126);
    float m = __int_as_float((ix & 0x007fffff) | 0x3f000000);
    if (m < 0.707106781186547524f) { e = __fadd_rn(e, -1.0f); m = __fadd_rn(m, m); }
    m = __fadd_rn(m, -1.0f);
    float z = __fmul_rn(m, m);
    float y = 7.0376836292e-2f;
    y = __fmaf_rn(y, m, -1.1514610310e-1f);
    y = __fmaf_rn(y, m, 1.1676998740e-1f);
    y = __fmaf_rn(y, m, -1.2420140846e-1f);
    y = __fmaf_rn(y, m, 1.4249322787e-1f);
    y = __fmaf_rn(y, m, -1.6668057665e-1f);
    y = __fmaf_rn(y, m, 2.0000714765e-1f);
    y = __fmaf_rn(y, m, -2.4999993993e-1f);
    y = __fmaf_rn(y, m, 3.3333331174e-1f);
    y = __fmul_rn(__fmul_rn(y, m), z);
    y = __fmaf_rn(e, -2.12194440e-4f, y);
    y = __fmaf_rn(z, -0.5f, y);
    float r = __fadd_rn(m, y);
    r = __fmaf_rn(e, 0.693359375f, r);
    return r;
}

__device__ __forceinline__ float xla_exp(float x) {
    float xc = fminf(fmaxf(x, -87.33654f), 88.72283f);
    float m = floorf(__fmaf_rn(xc, 1.44269504088896341f, 0.5f));
    float r = __fmaf_rn(m, -0.693359375f, xc);
    r = __fmaf_rn(m, 2.12194440e-4f, r);
    float r2 = __fmul_rn(r, r);
    float p = 1.9875691500e-4f;
    p = __fmaf_rn(p, r, 1.3981999507e-3f);
    p = __fmaf_rn(p, r, 8.3334519073e-3f);
    p = __fmaf_rn(p, r, 4.1665795894e-2f);
    p = __fmaf_rn(p, r, 1.6666665459e-1f);
    p = __fmaf_rn(p, r, 5.0000001201e-1f);
    float y = __fadd_rn(__fmaf_rn(p, r2, r), 1.0f);
    return __fmul_rn(y, __int_as_float(((int)m + 127) << 23));
}

__device__ __forceinline__ float xla_expm1(float x) {
    if (fabsf(x) < 1e-5f) return __fmaf_rn(__fmul_rn(0.5f, x), x, x);
    return __fadd_rn(xla_exp(x), -1.0f);
}

__device__ __forceinline__ float xla_elu(float x) {
    return (x > 0.0f) ? x : xla_expm1(x);
}

// ---------------- threefry2x32 (JAX bit-exact) ------------------------------
__device__ __forceinline__ uint32_t rotl32(uint32_t v, int r) {
    return (v << r) | (v >> (32 - r));
}

__device__ __forceinline__ void threefry2x32(uint32_t k0, uint32_t k1,
                                             uint32_t x0, uint32_t x1,
                                             uint32_t& o0, uint32_t& o1) {
    uint32_t ks2 = k0 ^ k1 ^ 0x1BD11BDAu;
    x0 += k0; x1 += k1;
    x0 += x1; x1 = rotl32(x1, 13); x1 ^= x0;
    x0 += x1; x1 = rotl32(x1, 15); x1 ^= x0;
    x0 += x1; x1 = rotl32(x1, 26); x1 ^= x0;
    x0 += x1; x1 = rotl32(x1,  6); x1 ^= x0;
    x0 += k1; x1 += ks2 + 1u;
    x0 += x1; x1 = rotl32(x1, 17); x1 ^= x0;
    x0 += x1; x1 = rotl32(x1, 29); x1 ^= x0;
    x0 += x1; x1 = rotl32(x1, 16); x1 ^= x0;
    x0 += x1; x1 = rotl32(x1, 24); x1 ^= x0;
    x0 += ks2; x1 += k0 + 2u;
    x0 += x1; x1 = rotl32(x1, 13); x1 ^= x0;
    x0 += x1; x1 = rotl32(x1, 15); x1 ^= x0;
    x0 += x1; x1 = rotl32(x1, 26); x1 ^= x0;
    x0 += x1; x1 = rotl32(x1,  6); x1 ^= x0;
    x0 += k0; x1 += k1 + 3u;
    x0 += x1; x1 = rotl32(x1, 17); x1 ^= x0;
    x0 += x1; x1 = rotl32(x1, 29); x1 ^= x0;
    x0 += x1; x1 = rotl32(x1, 16); x1 ^= x0;
    x0 += x1; x1 = rotl32(x1, 24); x1 ^= x0;
    x0 += k1; x1 += ks2 + 4u;
    x0 += x1; x1 = rotl32(x1, 13); x1 ^= x0;
    x0 += x1; x1 = rotl32(x1, 15); x1 ^= x0;
    x0 += x1; x1 = rotl32(x1, 26); x1 ^= x0;
    x0 += x1; x1 = rotl32(x1,  6); x1 ^= x0;
    x0 += ks2; x1 += k0 + 5u;
    o0 = x0; o1 = x1;
}

__device__ __forceinline__ uint32_t jax_bits32(uint32_t k0, uint32_t k1, uint32_t i) {
    uint32_t o0, o1;
    threefry2x32(k0, k1, 0u, i, o0, o1);
    return o0 ^ o1;
}

// ---------------- counter sync helpers --------------------------------------
__device__ __forceinline__ void role_signal(int t, int slot) {
    __threadfence();
    __syncthreads();
    if (threadIdx.x == 0) atomicAdd(&g_cnt[t][slot], 1);
}

__device__ __forceinline__ void role_wait(int t, int slot, int target) {
    if (threadIdx.x == 0) {
        while (atomicAdd(&g_cnt[t][slot], 0) < target) __nanosleep(64);
        __threadfence();
    }
    __syncthreads();
}

// ---------------- guarded float4 load ---------------------------------------
__device__ __forceinline__ float4 load_f4_guard(const float* __restrict__ src,
                                                size_t base, int k, int Klim) {
    if (k + 3 < Klim) return *reinterpret_cast<const float4*>(&src[base]);
    float4 v;
    v.x = (k + 0 < Klim) ? src[base + 0] : 0.f;
    v.y = (k + 1 < Klim) ? src[base + 1] : 0.f;
    v.z = (k + 2 < Klim) ? src[base + 2] : 0.f;
    v.w = (k + 3 < Klim) ? src[base + 3] : 0.f;
    return v;
}

// ---------------- templated GEMM core: BMxBN, double-buffered ----------------
// Per-output arithmetic: locked ascending-k single-accumulator FMA chain over
// BK=16 tiles — byte-identical to R13.
#define SMEM_BYTES 25088   // sizeof largest variant (64x128)

template<int BM, int BN>
__device__ void gemm_core_t(char* smraw,
    const float* __restrict__ A, const float* __restrict__ W,
    const float* __restrict__ bias, float* __restrict__ C,
    int K, int N, bool act, bool fuse,
    const float* __restrict__ feat, int concatK, int bm, int bn)
{
    struct Sm { float As[2][16][BM + 4]; float Ws[2][16][BN]; };
    Sm* sm = reinterpret_cast<Sm*>(smraw);
    constexpr int TM = BM / 16;
    constexpr int TN = BN / 16;
    constexpr int NW = BN / 64;          // float4 W loads per thread
    const int lda = fuse ? concatK : K;
    const int tid = threadIdx.x;
    const int tx = tid & 15;
    const int ty = tid >> 4;
    const int arow = tid >> 2, ac4 = tid & 3;          // A staging (tid < BM*4)
    const int wrow  = (NW == 2) ? (tid >> 5) : (tid >> 4);
    const int wcol4 = (NW == 2) ? (tid & 31) : (tid & 15);

    float acc[TM][TN];
#pragma unroll
    for (int i = 0; i < TM; i++)
#pragma unroll
        for (int j = 0; j < TN; j++) acc[i][j] = 0.f;

    const int ntiles = (K + 15) >> 4;

    float4 aR, wR0, wR1;
    auto load_tile = [&](int k0) {
        if (BM * 4 == 256 || tid < BM * 4) {
            int ka = k0 + ac4 * 4;
            if (fuse && ka >= concatK)
                aR = load_f4_guard(feat, (size_t)(bm + arow) * FDIM + (ka - concatK), ka, K);
            else
                aR = load_f4_guard(A, (size_t)(bm + arow) * lda + ka, ka, K);
        }
        int col = bn + wcol4 * 4;
        int kw0 = k0 + wrow;
        if (kw0 < K) {
            if (col + 3 < N) wR0 = *reinterpret_cast<const float4*>(&W[(size_t)kw0 * N + col]);
            else wR0 = load_f4_guard(W, (size_t)kw0 * N + col, col, N);
        } else wR0 = make_float4(0.f, 0.f, 0.f, 0.f);
        if (NW == 2) {
            int kw1 = k0 + wrow + 8;
            if (kw1 < K) {
                if (col + 3 < N) wR1 = *reinterpret_cast<const float4*>(&W[(size_t)kw1 * N + col]);
                else wR1 = load_f4_guard(W, (size_t)kw1 * N + col, col, N);
            } else wR1 = make_float4(0.f, 0.f, 0.f, 0.f);
        }
    };
    auto store_tile = [&](int buf) {
        if (BM * 4 == 256 || tid < BM * 4) {
            sm->As[buf][ac4 * 4 + 0][arow] = aR.x;
            sm->As[buf][ac4 * 4 + 1][arow] = aR.y;
            sm->As[buf][ac4 * 4 + 2][arow] = aR.z;
            sm->As[buf][ac4 * 4 + 3][arow] = aR.w;
        }
        *reinterpret_cast<float4*>(&sm->Ws[buf][wrow][wcol4 * 4]) = wR0;
        if (NW == 2)
            *reinterpret_cast<float4*>(&sm->Ws[buf][wrow + 8][wcol4 * 4]) = wR1;
    };

    load_tile(0);
    store_tile(0);
    __syncthreads();

    int buf = 0;
    for (int tI = 0; tI < ntiles; tI++) {
        const bool more = (tI + 1 < ntiles);
        if (more) load_tile((tI + 1) << 4);

#pragma unroll
        for (int kk = 0; kk < 16; kk++) {
            float a_[TM];
            if (TM == 4) {
                float4 av = *reinterpret_cast<const float4*>(&sm->As[buf][kk][ty * 4]);
                a_[0] = av.x; a_[1] = av.y; a_[2] = av.z; a_[TM - 1] = av.w;
            } else {
                float2 av = *reinterpret_cast<const float2*>(&sm->As[buf][kk][ty * 2]);
                a_[0] = av.x; a_[TM - 1] = av.y;
            }
            float w_[TN];
            {
                float4 wv0 = *reinterpret_cast<const float4*>(&sm->Ws[buf][kk][tx * 4]);
                w_[0] = wv0.x; w_[1] = wv0.y; w_[2] = wv0.z; w_[3] = wv0.w;
            }
            if (TN == 8) {
                float4 wv1 = *reinterpret_cast<const float4*>(&sm->Ws[buf][kk][64 + tx * 4]);
                w_[TN - 4] = wv1.x; w_[TN - 3] = wv1.y; w_[TN - 2] = wv1.z; w_[TN - 1] = wv1.w;
            }
#pragma unroll
            for (int i = 0; i < TM; i++)
#pragma unroll
                for (int j = 0; j < TN; j++)
                    acc[i][j] = __fmaf_rn(a_[i], w_[j], acc[i][j]);
        }
        if (more) {
            store_tile(buf ^ 1);
            __syncthreads();
            buf ^= 1;
        }
    }

    const bool fullN = (bn + BN <= N);
#pragma unroll
    for (int i = 0; i < TM; i++) {
        int row = bm + ty * TM + i;
#pragma unroll
        for (int h = 0; h < TN / 4; h++) {
            int colb = bn + h * 64 + tx * 4;
            float v[4];
#pragma unroll
            for (int j = 0; j < 4; j++) {
                float x = acc[i][h * 4 + j];
                int col = colb + j;
                if (col < N) {
                    if (bias) x = __fadd_rn(x, bias[col]);
                    if (act) x = xla_elu(x);
                }
                v[j] = x;
            }
            if (fullN) {
                *reinterpret_cast<float4*>(&C[(size_t)row * N + colb]) =
                    make_float4(v[0], v[1], v[2], v[3]);
            } else {
#pragma unroll
                for (int j = 0; j < 4; j++)
                    if (colb + j < N) C[(size_t)row * N + colb + j] = v[j];
            }
        }
    }
}

// ---------------- gru element (identical arithmetic to R11..R13) -------------
__device__ __forceinline__ void gru_elem(int i4) {
    int b = i4 >> 9;
    int j4 = i4 & 511;
    const float4* gib = reinterpret_cast<const float4*>(g_gi + (size_t)b * G3);
    const float4* ghb = reinterpret_cast<const float4*>(g_gh + (size_t)b * G3);
    float4 ir4 = gib[j4],        hr4 = ghb[j4];
    float4 iz4 = gib[512 + j4],  hz4 = ghb[512 + j4];
    float4 in4 = gib[1024 + j4], hn4 = ghb[1024 + j4];
    float4 hp4 = reinterpret_cast<const float4*>(g_h)[i4];
    float4 o;
    {
        float r  = xla_sigmoid(__fadd_rn(ir4.x, hr4.x));
        float zg = xla_sigmoid(__fadd_rn(iz4.x, hz4.x));
        float n  = xla_tanh(__fmaf_rn(r, hn4.x, in4.x));
        o.x = __fmaf_rn(zg, hp4.x, __fmul_rn(__fsub_rn(1.0f, zg), n));
    }
    {
        float r  = xla_sigmoid(__fadd_rn(ir4.y, hr4.y));
        float zg = xla_sigmoid(__fadd_rn(iz4.y, hz4.y));
        float n  = xla_tanh(__fmaf_rn(r, hn4.y, in4.y));
        o.y = __fmaf_rn(zg, hp4.y, __fmul_rn(__fsub_rn(1.0f, zg), n));
    }
    {
        float r  = xla_sigmoid(__fadd_rn(ir4.z, hr4.z));
        float zg = xla_sigmoid(__fadd_rn(iz4.z, hz4.z));
        float n  = xla_tanh(__fmaf_rn(r, hn4.z, in4.z));
        o.z = __fmaf_rn(zg, hp4.z, __fmul_rn(__fsub_rn(1.0f, zg), n));
    }
    {
        float r  = xla_sigmoid(__fadd_rn(ir4.w, hr4.w));
        float zg = xla_sigmoid(__fadd_rn(iz4.w, hz4.w));
        float n  = xla_tanh(__fmaf_rn(r, hn4.w, in4.w));
        o.w = __fmaf_rn(zg, hp4.w, __fmul_rn(__fsub_rn(1.0f, zg), n));
    }
    reinterpret_cast<float4*>(g_h)[i4] = o;
}

// ---------------- per-step pipelined mega-kernel -----------------------------
// 1D grid, 960 blocks, range-decoded roles in dependency order:
//  [0,128)   gru (grid-stride)            -> signal 0
//  [128,256) q1  32x64  (wait 0=128)      -> signal 1
//  [256,448) gh  64x128 (wait 0=128)      [skip at last]
//  [448,480) p1  64x128 (wait 0=128)      -> signal 2
//  [480,608) post 32x64 (wait 1=128)      -> signal 3
//  [608,640) prior 64x128 (wait 2=32)
//  [640,768) sample+x (wait 3=128)        -> signal 4   [skip at last]
//  [768,960) gi  64x128 (wait 4=128)      [skip at last]
__global__ __launch_bounds__(256) void step_kernel(
    const float* __restrict__ W_ih, const float* __restrict__ W_hh,
    const float* __restrict__ Wp1,  const float* __restrict__ Wq1,
    const float* __restrict__ Wp2,  const float* __restrict__ Wq2,
    const float* __restrict__ b_ih, const float* __restrict__ b_hh,
    const float* __restrict__ bp1,  const float* __restrict__ bq1,
    const float* __restrict__ bp2,  const float* __restrict__ bq2,
    const float* __restrict__ W_in, const float* __restrict__ b_in,
    const int* __restrict__ actions,
    const float* __restrict__ feat,
    float* __restrict__ out_prior, float* __restrict__ out_post,
    int t, int last)
{
    __shared__ __align__(16) char smraw[SMEM_BYTES];
    const int gb = blockIdx.x;              // 0..959

    if (gb < 128) {          // gru: h_t = gru(gi_t, gh_t, h_{t-1})
        const int total = B * GRU_H / 4;    // 131072 float4 units
        for (int i4 = gb * 256 + threadIdx.x; i4 < total; i4 += 128 * 256)
            gru_elem(i4);
        role_signal(t, 0);
    } else if (gb < 256) {   // q1 = elu([h|feat] @ Wq1 + bq1)  K=3072, N=1000
        int r = gb - 128;
        role_wait(t, 0, 128);
        int bm = (r & 7) * 32, bn = (r >> 3) * 64;
        gemm_core_t<32, 64>(smraw, g_h, Wq1, bq1, g_q1, GRU_H + FDIM, MLP,
                            true, true, feat, GRU_H, bm, bn);
        role_signal(t, 1);
    } else if (gb < 448) {   // gh_{t+1} = h @ W_hh + b_hh      K=2048, N=6144
        if (last) return;
        int r = gb - 256;
        role_wait(t, 0, 128);
        gemm_core_t<64, 128>(smraw, g_h, W_hh, b_hh, g_gh, GRU_H, G3,
                             false, false, nullptr, 0, (r & 3) * 64, (r >> 2) * 128);
    } else if (gb < 480) {   // p1 = elu(h @ Wp1 + bp1)         K=2048, N=1000
        int r = gb - 448;
        role_wait(t, 0, 128);
        gemm_core_t<64, 128>(smraw, g_h, Wp1, bp1, g_p1, GRU_H, MLP,
                             true, false, nullptr, 0, (r & 3) * 64, (r >> 2) * 128);
        role_signal(t, 2);
    } else if (gb < 608) {   // post = q1 @ Wq2 + bq2           K=1000, N=1024
        int r = gb - 480;
        role_wait(t, 1, 128);
        int bm = (r & 7) * 32, bn = (r >> 3) * 64;
        gemm_core_t<32, 64>(smraw, g_q1, Wq2, bq2, out_post, MLP, ZF,
                            false, false, nullptr, 0, bm, bn);
        role_signal(t, 3);
    } else if (gb < 640) {   // prior = p1 @ Wp2 + bp2          K=1000, N=1024
        int r = gb - 608;
        role_wait(t, 2, 32);
        gemm_core_t<64, 128>(smraw, g_p1, Wp2, bp2, out_prior, MLP, ZF,
                             false, false, nullptr, 0, (r & 3) * 64, (r >> 2) * 128);
    } else if (gb < 768) {   // sample z_t + x_{t+1}  (2 batches per block)
        if (last) return;
        int bid = gb - 640;                 // 0..127
        role_wait(t, 3, 128);

        __shared__ int   idx[2][32];
        __shared__ float wgt[2][32];

        int warp = threadIdx.x >> 5;
        int lane = threadIdx.x & 31;
        int half = warp >> 2;
        int b = bid * 2 + half;
        int cw = warp & 3;

        uint32_t k0, k1;
        threefry2x32(0u, 42u, 0u, (uint32_t)t, k0, k1);
        const float TINY = 1.1754943508222875e-38f;

        for (int c = cw; c < 32; c += 4) {
            float l = out_post[(size_t)b * ZF + c * 32 + lane];
            uint32_t i = (uint32_t)((b * 32 + c) * 32 + lane);
            uint32_t bits = jax_bits32(k0, k1, i);
            float f = __fadd_rn(__uint_as_float((bits >> 9) | 0x3f800000u), -1.0f);
            float u = fmaxf(TINY, __fadd_rn(f, TINY));
            float g = -xla_log(-xla_log(u));
            float v = __fadd_rn(l, g);

            float bv = v; int bi = lane;
#pragma unroll
            for (int off = 16; off > 0; off >>= 1) {
                float ov = __shfl_down_sync(0xffffffffu, bv, off);
                int   oi = __shfl_down_sync(0xffffffffu, bi, off);
                if (ov > bv || (ov == bv && oi < bi)) { bv = ov; bi = oi; }
            }
            bi = __shfl_sync(0xffffffffu, bi, 0);

            float m = l;
#pragma unroll
            for (int off = 16; off > 0; off >>= 1)
                m = fmaxf(m, __shfl_xor_sync(0xffffffffu, m, off));
            float e = xla_exp(__fadd_rn(l, -m));
            float s = 0.f;
#pragma unroll
            for (int ll = 0; ll < 32; ll++)
                s = __fadd_rn(s, __shfl_sync(0xffffffffu, e, ll));
            float p = __fdiv_rn(e, s);
            float psel = __shfl_sync(0xffffffffu, p, bi);
            if (lane == 0) {
                idx[half][c] = bi;
                wgt[half][c] = __fadd_rn(__fadd_rn(1.0f, psel), -psel);  // fl(1+p)-p
            }
        }
        __syncthreads();

        int xh = threadIdx.x >> 7;
        int bx = bid * 2 + xh;
        int a = actions[t * B + bx];        // act_seq[t+1] = actions[t]
        for (int j = threadIdx.x & 127; j < MLP; j += 128) {
            float s = 0.f;
#pragma unroll
            for (int c = 0; c < 32; c++)
                s = __fmaf_rn(wgt[xh][c], W_in[(size_t)(c * 32 + idx[xh][c]) * MLP + j], s);
            s = __fmaf_rn(1.0f, W_in[(size_t)(ZF + a) * MLP + j], s);
            s = __fadd_rn(s, b_in[j]);
            g_x[bx * MLP + j] = xla_elu(s);
        }
        role_signal(t, 4);
    } else {                 // gi_{t+1} = x @ W_ih + b_ih      K=1000, N=6144
        if (last) return;
        int r = gb - 768;
        role_wait(t, 4, 128);
        gemm_core_t<64, 128>(smraw, g_x, W_ih, b_ih, g_gi, MLP, G3,
                             false, false, nullptr, 0, (r & 3) * 64, (r >> 2) * 128);
    }
}

// ---------------- prologue kernels -------------------------------------------
__global__ __launch_bounds__(256) void reset_kernel()
{
    int i = blockIdx.x * blockDim.x + threadIdx.x;
    if (i < T_STEPS * 5) (&g_cnt[0][0])[i] = 0;
    for (int j = i; j < B * GRU_H; j += gridDim.x * blockDim.x) g_h[j] = 0.f;
}

__global__ __launch_bounds__(256) void compute_x0_kernel(
    const float* __restrict__ W_in, const float* __restrict__ b_in)
{
    int b = blockIdx.x;
    for (int j = threadIdx.x; j < MLP; j += blockDim.x) {
        float s = W_in[(size_t)ZF * MLP + j];   // action 0 row, weight 1
        s = __fadd_rn(s, b_in[j]);
        g_x[b * MLP + j] = xla_elu(s);
    }
}

// prologue dual GEMM: gi_0 | gh_0 (z selects), grid (4, 48, 2)
__global__ __launch_bounds__(256) void gemm0_kernel(
    const float* __restrict__ W_ih, const float* __restrict__ W_hh,
    const float* __restrict__ b_ih, const float* __restrict__ b_hh)
{
    __shared__ __align__(16) char smraw[SMEM_BYTES];
    const int bm = blockIdx.x * 64;
    const int bn = blockIdx.y * 128;
    if (blockIdx.z == 0)
        gemm_core_t<64, 128>(smraw, g_x, W_ih, b_ih, g_gi, MLP, G3,
                             false, false, nullptr, 0, bm, bn);
    else
        gemm_core_t<64, 128>(smraw, g_h, W_hh, b_hh, g_gh, GRU_H, G3,
                             false, false, nullptr, 0, bm, bn);
}

// ---------------------------------------------------------------------------
extern "C" void kernel_launch(void* const* d_in, const int* in_sizes, int n_in,
                              void* d_out, int out_size)
{
    const float* features = (const float*)d_in[0];   // [64,256,1024]
    const int*   actions  = (const int*)  d_in[1];   // [64,256]
    const float* W_in = (const float*)d_in[2];
    const float* b_in = (const float*)d_in[3];
    const float* W_ih = (const float*)d_in[4];
    const float* W_hh = (const float*)d_in[5];
    const float* b_ih = (const float*)d_in[6];
    const float* b_hh = (const float*)d_in[7];
    const float* Wp1  = (const float*)d_in[8];
    const float* bp1  = (const float*)d_in[9];
    const float* Wp2  = (const float*)d_in[10];
    const float* bp2  = (const float*)d_in[11];
    const float* Wq1  = (const float*)d_in[12];
    const float* bq1  = (const float*)d_in[13];
    const float* Wq2  = (const float*)d_in[14];
    const float* bq2  = (const float*)d_in[15];
    float* out = (float*)d_out;                      // [2,64,256,32,32]

    reset_kernel<<<(B * GRU_H + 255) / 256, 256>>>();
    compute_x0_kernel<<<B, 256>>>(W_in, b_in);
    gemm0_kernel<<<dim3(4, 48, 2), 256>>>(W_ih, W_hh, b_ih, b_hh);

    for (int t = 0; t < T_STEPS; t++) {
        const float* feat_t = features + (size_t)t * B * FDIM;
        float* out_prior = out + (size_t)t * B * ZF;
        float* out_post  = out + ((size_t)(T_STEPS + t)) * B * ZF;

        step_kernel<<<960, 256>>>(
            W_ih, W_hh, Wp1, Wq1, Wp2, Wq2,
            b_ih, b_hh, bp1, bq1, bp2, bq2,
            W_in, b_in, actions, feat_t, out_prior, out_post,
            t, (t == T_STEPS - 1) ? 1 : 0);
    }
}